// round 15
// baseline (speedup 1.0000x reference)
#include <cuda_runtime.h>
#include <stdint.h>

#define Nn 4096
#define Cc 10
#define LMAX 128
#define S1 0.73105857863000489f      // sigmoid(1.0) in fp32
#define TPB 128
#define TCAP 1024

// ---------------- scratch (static device globals; zero-initialized) ----------
// Mutable state is reset by the FINAL block for the NEXT replay
// (first run relies on static zero-init).
__device__ int   g_colcnt[Nn];            // masked in-neighbor count of column k
__device__ int   g_colidx[Nn * LMAX];     // masked in-neighbor NODE ids of column k
__device__ int   g_deg[Nn];               // out-degree (masked rows only)
__device__ int   g_rowidx[Nn * LMAX];     // out-neighbor node ids (masked rows)
__device__ unsigned char g_diag[Nn];      // node has self-loop
__device__ unsigned char g_slab[Nn];      // label if masked, 255 if unmasked
__device__ float g_Eq[Cc * Nn];           // exp(preds[q,i]), node-indexed
__device__ float g_cep[Nn];               // per-node CE (overwritten every run)
__device__ float g_Qs[Cc * Cc];
__device__ float g_T[Cc * Cc];
__device__ float g_Si[Cc * Cc];
__device__ float g_Sc[Cc * Cc];
__device__ float g_Ncnt[Cc];
__device__ float g_Sdeg[Cc];
__device__ float g_W0[Cc];
__device__ int   g_qn;
__device__ int   g_qlist[Nn];             // masked node ids in node order
__device__ int          g_cnt2, g_done;   // barrier/arrival counters (self-reset)
__device__ volatile int g_flag2;

// build one masked row (128 threads, all 8 uint4 loads issued upfront)
__device__ __forceinline__ void build_row(const unsigned int* __restrict__ adj,
                                          int n, int tid) {
    const uint4* rowp = (const uint4*)(adj + (size_t)n * Nn);   // 1024 uint4
    uint4 a[8];
#pragma unroll
    for (int s = 0; s < 8; s++) a[s] = rowp[tid + s * TPB];
#pragma unroll
    for (int s = 0; s < 8; s++) {
        if (a[s].x | a[s].y | a[s].z | a[s].w) {
            int i4 = tid + s * TPB;
            unsigned parts[4] = {a[s].x, a[s].y, a[s].z, a[s].w};
#pragma unroll
            for (int u = 0; u < 4; u++) {
                if (parts[u]) {
                    int kk = i4 * 4 + u;
                    int ri = atomicAdd(&g_deg[n], 1);
                    if (ri < LMAX) g_rowidx[n * LMAX + ri] = kk;
                    int ci = atomicAdd(&g_colcnt[kk], 1);
                    if (ci < LMAX) g_colidx[kk * LMAX + ci] = n;
                    if (n == kk) g_diag[n] = 1;
                }
            }
        }
    }
}

__global__ void __launch_bounds__(TPB)
k_all(const float* __restrict__ preds,
      const int* __restrict__ labels,
      const unsigned int* __restrict__ mask,
      const unsigned int* __restrict__ adj,
      float* __restrict__ out) {
    __shared__ unsigned int scnt[Nn];         // 16KB node-indexed counters
    __shared__ int   s_touch[TCAP];           // 4KB touched node ids
    __shared__ float sTw[4 * Cc];             // per-warp T accumulators
    __shared__ unsigned int sICw[4 * Cc];     // per-warp packed (corr<<16|inter)
    __shared__ float sred[TPB];
    __shared__ int   s_wsum[4];
    __shared__ int   s_last, s_ntouch, s_ovf;

    const int tid = threadIdx.x, bi = blockIdx.x;
    const int lane = tid & 31, wid = tid >> 5;
    const int nblk = gridDim.x;

    // zero smem counters once per block
    {
        uint4* s4 = (uint4*)scnt;
#pragma unroll
        for (int i = tid; i < Nn / 4; i += TPB) s4[i] = make_uint4(0, 0, 0, 0);
    }

    // ---- block 0: rank scan (qlist / slab / qn) — build doesn't need it ----
    if (bi == 0) {
        int base = tid * 32;                      // 128 threads x 32 nodes
        unsigned mv = 0; int cnt = 0;
#pragma unroll
        for (int j = 0; j < 32; j++) {
            if (mask[base + j] != 0u) { mv |= 1u << j; cnt++; }
        }
        int inc = cnt;
#pragma unroll
        for (int o = 1; o < 32; o <<= 1) {
            int y = __shfl_up_sync(0xFFFFFFFFu, inc, o);
            if (lane >= o) inc += y;
        }
        if (lane == 31) s_wsum[wid] = inc;
        __syncthreads();
        int woff = 0;
#pragma unroll
        for (int k = 0; k < 4; k++) if (k < wid) woff += s_wsum[k];
        int rk = woff + inc - cnt;                // exclusive prefix
#pragma unroll
        for (int j = 0; j < 32; j++) {
            int pp = base + j;
            if ((mv >> j) & 1u) {
                g_qlist[rk] = pp;
                g_slab[pp] = (unsigned char)labels[pp];
                rk++;
            } else g_slab[pp] = 255;
        }
        if (tid == TPB - 1) g_qn = rk;
        __syncthreads();
    }

    // ================= Phase 1: CE/Eq + build =================
    for (int pair = bi; pair < Nn / 2; pair += nblk) {
        int n0 = 2 * pair, n1 = n0 + 1;
        // CE + Eq for the two nodes (warps 0 and 1); per-node output, no syncs
        if (wid < 2) {
            int n = n0 + wid;
            float r = 0.f, e = 0.f;
            if (lane < Cc) {
                r = preds[n * Cc + lane];
                e = __expf(r);
                g_Eq[lane * Nn + n] = e;
            }
            float se = e;
#pragma unroll
            for (int o = 16; o > 0; o >>= 1) se += __shfl_down_sync(0xFFFFFFFFu, se, o);
            se = __shfl_sync(0xFFFFFFFFu, se, 0);
            int l = labels[n];
            float rl = __shfl_sync(0xFFFFFFFFu, r, l);
            if (lane == 0) g_cep[n] = __logf(se) - rl;   // -log softmax[l]
        }
        if (mask[n0] != 0u) build_row(adj, n0, tid);
        if (mask[n1] != 0u) build_row(adj, n1, tid);
    }

    // ===== grid barrier (guaranteed-resident grid; cannot deadlock) =====
    __syncthreads();
    if (tid == 0) {
        __threadfence();
        if (atomicAdd(&g_cnt2, 1) == nblk - 1) { __threadfence(); g_flag2 = 1; }
        else { while (g_flag2 == 0) __nanosleep(32); }
        __threadfence();
    }
    __syncthreads();
    const int qn = g_qn;

    // ================= Phase 2: one masked row per block-iteration ==========
    for (int r = bi; r < qn; r += nblk) {
        const int p = g_qlist[r];
        if (tid == 0) { s_ntouch = 0; s_ovf = 0; }
        if (tid < 4 * Cc) { sTw[tid] = 0.f; sICw[tid] = 0u; }
        int dgi = g_deg[p];
        int dp = min(dgi, LMAX);
        int my_nbr = (tid < dp) ? g_rowidx[p * LMAX + tid] : -1;
        __syncthreads();
        int cp = (int)g_slab[p];

        // expansion: 4 warps over out-neighbors; warp-aggregated appends.
        // Neighbor reload from g_rowidx is L1-hot (same line as my_nbr load).
        for (int i = wid; i < dp; i += 4) {
            int k = g_rowidx[p * LMAX + i];
            int c = min(g_colcnt[k], LMAX);
            const int* cl = g_colidx + k * LMAX;
            for (int jj = 0; jj < c; jj += 32) {
                int j = jj + lane;
                int nd = 0; unsigned old = 1u;
                if (j < c) { nd = cl[j]; old = atomicAdd(&scnt[nd], 1u); }
                unsigned ball = __ballot_sync(0xFFFFFFFFu, old == 0u);
                if (ball) {
                    int leader = __ffs(ball) - 1;
                    int base = 0;
                    if (lane == leader) base = atomicAdd(&s_ntouch, __popc(ball));
                    base = __shfl_sync(0xFFFFFFFFu, base, leader);
                    if (old == 0u) {
                        int off = __popc(ball & ((1u << lane) - 1u));
                        if (base + off < TCAP) s_touch[base + off] = nd; else s_ovf = 1;
                    }
                }
            }
        }
        // corr bits: masked out-neighbors lacking a self-loop (dp <= TPB)
        {
            int q = my_nbr; unsigned old = 1u;
            if (q >= 0 && g_slab[q] != 255 && !g_diag[q]) old = atomicAdd(&scnt[q], 65536u);
            unsigned ball = __ballot_sync(0xFFFFFFFFu, old == 0u);
            if (ball) {
                int leader = __ffs(ball) - 1;
                int base = 0;
                if (lane == leader) base = atomicAdd(&s_ntouch, __popc(ball));
                base = __shfl_sync(0xFFFFFFFFu, base, leader);
                if (old == 0u) {
                    int off = __popc(ball & ((1u << lane) - 1u));
                    if (base + off < TCAP) s_touch[base + off] = q; else s_ovf = 1;
                }
            }
        }
        __syncthreads();

        float degp = (float)dgi;
        float wp = __fdividef(1.f, g_Eq[cp * Nn + p]);          // exp(-pos)
        float v0 = __fdividef(1.f, 1.f + __expf(1.f + S1 * degp));
        const float* eqrow = g_Eq + cp * Nn;
        float* myT = sTw + wid * Cc;
        unsigned int* myIC = sICw + wid * Cc;

        if (!s_ovf) {
            int nt = s_ntouch;
            for (int j = tid; j < nt; j += TPB) {
                int i = s_touch[j];
                unsigned w = scnt[i];
                scnt[i] = 0u;                          // restore for next row
                int lq = (int)g_slab[i];
                if (lq == cp) continue;                // same class never used
                float inter = (float)(w & 0xFFFFu);
                float corr  = (float)(w >> 16);
                float sub = degp - inter - corr;
                float arg = (1.0f + S1 * sub) / (1.0f + S1 * inter);
                float v = __fdividef(1.0f, 1.0f + __expf(arg));
                atomicAdd(&myT[lq], wp * eqrow[i] * (v - v0));
                atomicAdd(&myIC[lq], w);               // packed: corr<<16 | inter
            }
        } else {                                       // fallback: dense scan
            for (int i = tid; i < Nn; i += TPB) {
                unsigned w = scnt[i];
                if (!w) continue;
                scnt[i] = 0u;
                int lq = (int)g_slab[i];
                if (lq == 255 || lq == cp) continue;
                float inter = (float)(w & 0xFFFFu);
                float corr  = (float)(w >> 16);
                float sub = degp - inter - corr;
                float arg = (1.0f + S1 * sub) / (1.0f + S1 * inter);
                float v = __fdividef(1.0f, 1.0f + __expf(arg));
                atomicAdd(&myT[lq], wp * eqrow[i] * (v - v0));
                atomicAdd(&myIC[lq], w);
            }
        }
        __syncthreads();
        if (tid < Cc) {
            float tT = 0.f; unsigned tIC = 0u;
#pragma unroll
            for (int w = 0; w < 4; w++) {
                tT += sTw[w * Cc + tid];
                tIC += sICw[w * Cc + tid];             // per-row Σinter < 65536
            }
            if (tid != cp) {
                int idx = cp * Cc + tid;
                if (tT != 0.f) atomicAdd(&g_T[idx], tT);
                if (tIC) {
                    atomicAdd(&g_Si[idx], (float)(tIC & 0xFFFFu));
                    atomicAdd(&g_Sc[idx], (float)(tIC >> 16));
                }
            }
            atomicAdd(&g_Qs[tid * Cc + cp], g_Eq[tid * Nn + p]);   // node as q
        }
        if (tid == 0) {
            atomicAdd(&g_Ncnt[cp], 1.f);
            atomicAdd(&g_Sdeg[cp], degp);
            atomicAdd(&g_W0[cp], wp * v0);
        }
        __syncthreads();                               // protect smem for next row
    }

    // ===== arrival + fused final (output, then state reset for next replay) ====
    if (tid == 0) { __threadfence(); s_last = (atomicAdd(&g_done, 1) == nblk - 1); }
    __syncthreads();
    if (!s_last) return;
    __threadfence();

    float ce = 0.f;
#pragma unroll
    for (int k = 0; k < Nn / TPB; k++) ce += g_cep[tid + k * TPB];
    sred[tid] = ce;
    __syncthreads();
    for (int o = TPB / 2; o > 0; o >>= 1) {
        if (tid < o) sred[tid] += sred[tid + o];
        __syncthreads();
    }
    float ce_tot = sred[0];
    __syncthreads();

    float contrib = 0.f;
    if (tid < Cc * Cc) {
        int i = tid / Cc, j = tid - i * Cc;
        if (i != j) {
            float Si = g_Si[tid];
            float Ssub = g_Sdeg[i] * g_Ncnt[j] - Si - g_Sc[tid];   // exact ints in f32
            if (Si > 0.f && Ssub > 0.f) {
                float T = g_T[tid] + g_W0[i] * g_Qs[tid];
                float ni = fmaxf(g_Ncnt[i], 1.f);
                float nj = fmaxf(g_Ncnt[j], 1.f);
                contrib = T / (ni * nj);
            }
        }
    }
    sred[tid] = contrib;
    __syncthreads();
    for (int o = TPB / 2; o > 0; o >>= 1) {
        if (tid < o) sred[tid] += sred[tid + o];
        __syncthreads();
    }
    if (tid == 0) out[0] = ce_tot / (float)Nn + 0.001f * sred[0];

    // reset state for the NEXT replay (all blocks arrived; no races)
    for (int i = tid; i < Nn; i += TPB) { g_colcnt[i] = 0; g_deg[i] = 0; g_diag[i] = 0; }
    if (tid < Cc * Cc) { g_T[tid] = 0.f; g_Si[tid] = 0.f; g_Sc[tid] = 0.f; g_Qs[tid] = 0.f; }
    if (tid < Cc) { g_Ncnt[tid] = 0.f; g_Sdeg[tid] = 0.f; g_W0[tid] = 0.f; }
    if (tid == 0) { g_done = 0; g_cnt2 = 0; g_flag2 = 0; __threadfence(); }
}

// ---------------- launch -----------------------------------------------------
extern "C" void kernel_launch(void* const* d_in, const int* in_sizes, int n_in,
                              void* d_out, int out_size) {
    const float* preds  = (const float*)d_in[0];
    const int*   labels = (const int*)d_in[1];
    const unsigned int* mask = (const unsigned int*)d_in[2];
    const unsigned int* adj  = (const unsigned int*)d_in[3];

    int sms = 148;
    cudaDeviceGetAttribute(&sms, cudaDevAttrMultiProcessorCount, 0);
    int bpm = 0;
    cudaOccupancyMaxActiveBlocksPerMultiprocessor(&bpm, k_all, TPB, 0);
    if (bpm < 1) bpm = 1;
    int grid = sms * bpm;                 // guaranteed co-resident -> barrier safe

    k_all<<<grid, TPB>>>(preds, labels, mask, adj, (float*)d_out);
}

// round 16
// speedup vs baseline: 1.1309x; 1.1309x over previous
#include <cuda_runtime.h>
#include <stdint.h>

#define Nn 4096
#define Cc 10
#define LMAX 128
#define S1 0.73105857863000489f      // sigmoid(1.0) in fp32
#define TCAP 768
#define PTPB 128                     // k_process threads (4 warps)
#define PGRID 2560                   // k_process grid (>= qn with wide margin)

// ---------------- scratch (static device globals; zero-initialized) ----------
// g_colcnt/g_deg/g_diag and class accumulators are zeroed by the FINAL block
// of k_process for the NEXT replay (first run uses static zero-init).
__device__ int   g_colcnt[Nn];            // masked in-neighbor count of column k
__device__ int   g_colidx[Nn * LMAX];     // masked in-neighbor NODE ids of column k
__device__ int   g_deg[Nn];               // out-degree (masked rows only)
__device__ int   g_rowidx[Nn * LMAX];     // out-neighbor node ids (masked rows)
__device__ unsigned char g_diag[Nn];      // node has self-loop
__device__ unsigned char g_slab[Nn];      // label if masked, 255 if unmasked
__device__ float g_Eq[Cc * Nn];           // exp(preds[q,i]), node-indexed
__device__ float g_Qs[Cc * Cc];
__device__ float g_T[Cc * Cc];
__device__ float g_Si[Cc * Cc];
__device__ float g_Sc[Cc * Cc];
__device__ float g_Ncnt[Cc];
__device__ float g_Sdeg[Cc];
__device__ float g_W0[Cc];
__device__ float g_cepart[2048];          // per-block CE partials (overwritten)
__device__ int   g_qn;
__device__ int   g_qlist[Nn];             // masked node ids in node order
__device__ int   g_done;                  // arrival counter (self-resetting)

// ============ Kernel 1: build + CE/Eq + rank scan ==============
__device__ __forceinline__ void decode4(uint4 x0, uint4 x1, uint4 x2, uint4 x3,
                                        int tid, int n) {
#pragma unroll
    for (int s = 0; s < 4; s++) {
        uint4 x = (s == 0) ? x0 : (s == 1) ? x1 : (s == 2) ? x2 : x3;
        if (x.x | x.y | x.z | x.w) {
            int i4 = tid + s * 256;
            unsigned parts[4] = {x.x, x.y, x.z, x.w};
#pragma unroll
            for (int u = 0; u < 4; u++) {
                if (parts[u]) {
                    int kk = i4 * 4 + u;
                    int ri = atomicAdd(&g_deg[n], 1);
                    if (ri < LMAX) g_rowidx[n * LMAX + ri] = kk;
                    int ci = atomicAdd(&g_colcnt[kk], 1);
                    if (ci < LMAX) g_colidx[kk * LMAX + ci] = n;
                    if (n == kk) g_diag[n] = 1;
                }
            }
        }
    }
}

__global__ void k_build(const float* __restrict__ preds,
                        const int* __restrict__ labels,
                        const unsigned int* __restrict__ mask,
                        const unsigned int* __restrict__ adj) {
    __shared__ float s_ce[2];
    __shared__ int s_wsum[8];
    int tid = threadIdx.x, bi = blockIdx.x;
    int lane = tid & 31, wid = tid >> 5;

    if (bi == 2048) {
        // rank scan: qlist (masked nodes in node order), qn, slab
        int base = tid * 16;
        unsigned mv = 0; int cnt = 0;
#pragma unroll
        for (int j = 0; j < 16; j++) {
            if (mask[base + j] != 0u) { mv |= 1u << j; cnt++; }
        }
        int inc = cnt;
#pragma unroll
        for (int o = 1; o < 32; o <<= 1) {
            int y = __shfl_up_sync(0xFFFFFFFFu, inc, o);
            if (lane >= o) inc += y;
        }
        if (lane == 31) s_wsum[wid] = inc;
        __syncthreads();
        int woff = 0;
#pragma unroll
        for (int k = 0; k < 8; k++) if (k < wid) woff += s_wsum[k];
        int rk = woff + inc - cnt;
#pragma unroll
        for (int j = 0; j < 16; j++) {
            int pp = base + j;
            if ((mv >> j) & 1u) {
                g_qlist[rk] = pp;
                g_slab[pp] = (unsigned char)labels[pp];
                rk++;
            } else g_slab[pp] = 255;
        }
        if (tid == 255) g_qn = rk;
        return;
    }

    int n0 = 2 * bi, n1 = 2 * bi + 1;
    bool has0 = (mask[n0] != 0u), has1 = (mask[n1] != 0u);
    const uint4* row0 = (const uint4*)(adj + (size_t)n0 * Nn);
    const uint4* row1 = (const uint4*)(adj + (size_t)n1 * Nn);
    uint4 a0, a1, a2, a3, b0, b1, b2, b3;
    if (has0) { a0 = row0[tid]; a1 = row0[tid + 256]; a2 = row0[tid + 512]; a3 = row0[tid + 768]; }
    if (has1) { b0 = row1[tid]; b1 = row1[tid + 256]; b2 = row1[tid + 512]; b3 = row1[tid + 768]; }

    // CE + Eq for this block's two nodes (warps 0/1) — hidden under adj stream
    if (wid < 2) {
        int n = 2 * bi + wid;
        float r = 0.f, e = 0.f;
        if (lane < Cc) {
            r = preds[n * Cc + lane];
            e = __expf(r);
            g_Eq[lane * Nn + n] = e;
        }
        float se = e;
#pragma unroll
        for (int o = 16; o > 0; o >>= 1) se += __shfl_down_sync(0xFFFFFFFFu, se, o);
        se = __shfl_sync(0xFFFFFFFFu, se, 0);
        int l = labels[n];
        float rl = __shfl_sync(0xFFFFFFFFu, r, l);
        if (lane == 0) s_ce[wid] = __logf(se) - rl;   // -log softmax[l]
    }
    __syncthreads();
    if (tid == 0) g_cepart[bi] = s_ce[0] + s_ce[1];

    if (has0) decode4(a0, a1, a2, a3, tid, n0);
    if (has1) decode4(b0, b1, b2, b3, tid, n1);
}

// ============ Kernel 2: one masked row per 128-thread block + fused final ====
__global__ void __launch_bounds__(PTPB)
k_process(float* __restrict__ out) {
    __shared__ unsigned int scnt[Nn];         // 16KB node-indexed counters
    __shared__ int   s_touch[TCAP];           // 3KB touched node ids
    __shared__ int   s_nbr[LMAX];             // out-neighbors of this row
    __shared__ int   s_ccnt[LMAX];            // PREFETCHED colcnt per neighbor
    __shared__ float sTw[4 * Cc];             // per-warp T accumulators
    __shared__ unsigned int sICw[4 * Cc];     // per-warp packed (corr<<16|inter)
    __shared__ float sred[PTPB];
    __shared__ int   s_last, s_ntouch, s_ovf;

    const int tid = threadIdx.x, bi = blockIdx.x;
    const int lane = tid & 31, wid = tid >> 5;
    const int qn = g_qn;

    if (bi < qn) {
        const int p = g_qlist[bi];
        if (tid == 0) { s_ntouch = 0; s_ovf = 0; }
        if (tid < 4 * Cc) { sTw[tid] = 0.f; sICw[tid] = 0u; }
        {   // zero counters
            uint4* s4 = (uint4*)scnt;
            for (int i = tid; i < Nn / 4; i += PTPB) s4[i] = make_uint4(0, 0, 0, 0);
        }
        int dgi = g_deg[p];
        int dp = min(dgi, LMAX);
        // stage neighbors AND prefetch their colcnt in one parallel step —
        // removes the 250-cycle dependent colcnt load from the per-list chain
        int my_nbr = -1, my_cc = 0;
        if (tid < dp) {
            my_nbr = g_rowidx[p * LMAX + tid];
            my_cc = g_colcnt[my_nbr];
            s_nbr[tid] = my_nbr;
            s_ccnt[tid] = my_cc;
        }
        __syncthreads();
        int cp = (int)g_slab[p];

        // expansion: 4 warps over out-neighbors; warp-aggregated appends
        for (int i = wid; i < dp; i += 4) {
            int k = s_nbr[i];
            int c = min(s_ccnt[i], LMAX);
            const int* cl = g_colidx + k * LMAX;
            for (int jj = 0; jj < c; jj += 32) {
                int j = jj + lane;
                int nd = 0; unsigned old = 1u;
                if (j < c) { nd = cl[j]; old = atomicAdd(&scnt[nd], 1u); }
                unsigned ball = __ballot_sync(0xFFFFFFFFu, old == 0u);
                if (ball) {
                    int leader = __ffs(ball) - 1;
                    int base = 0;
                    if (lane == leader) base = atomicAdd(&s_ntouch, __popc(ball));
                    base = __shfl_sync(0xFFFFFFFFu, base, leader);
                    if (old == 0u) {
                        int off = __popc(ball & ((1u << lane) - 1u));
                        if (base + off < TCAP) s_touch[base + off] = nd; else s_ovf = 1;
                    }
                }
            }
        }
        // corr bits: masked out-neighbors lacking a self-loop (dp <= PTPB)
        {
            int q = my_nbr; unsigned old = 1u;
            if (q >= 0 && g_slab[q] != 255 && !g_diag[q]) old = atomicAdd(&scnt[q], 65536u);
            unsigned ball = __ballot_sync(0xFFFFFFFFu, old == 0u);
            if (ball) {
                int leader = __ffs(ball) - 1;
                int base = 0;
                if (lane == leader) base = atomicAdd(&s_ntouch, __popc(ball));
                base = __shfl_sync(0xFFFFFFFFu, base, leader);
                if (old == 0u) {
                    int off = __popc(ball & ((1u << lane) - 1u));
                    if (base + off < TCAP) s_touch[base + off] = q; else s_ovf = 1;
                }
            }
        }
        __syncthreads();

        float degp = (float)dgi;
        float wp = __fdividef(1.f, g_Eq[cp * Nn + p]);          // exp(-pos)
        float v0 = __fdividef(1.f, 1.f + __expf(1.f + S1 * degp));
        const float* eqrow = g_Eq + cp * Nn;
        float* myT = sTw + wid * Cc;
        unsigned int* myIC = sICw + wid * Cc;

        if (!s_ovf) {
            int nt = s_ntouch;
            for (int j = tid; j < nt; j += PTPB) {
                int i = s_touch[j];
                unsigned w = scnt[i];
                int lq = (int)g_slab[i];
                if (lq == cp) continue;                // same class never used
                float inter = (float)(w & 0xFFFFu);
                float corr  = (float)(w >> 16);
                float sub = degp - inter - corr;
                float arg = (1.0f + S1 * sub) / (1.0f + S1 * inter);
                float v = __fdividef(1.0f, 1.0f + __expf(arg));
                atomicAdd(&myT[lq], wp * eqrow[i] * (v - v0));
                atomicAdd(&myIC[lq], w);               // packed: corr<<16 | inter
            }
        } else {                                       // fallback: dense scan
            for (int i = tid; i < Nn; i += PTPB) {
                unsigned w = scnt[i];
                if (!w) continue;
                int lq = (int)g_slab[i];
                if (lq == 255 || lq == cp) continue;
                float inter = (float)(w & 0xFFFFu);
                float corr  = (float)(w >> 16);
                float sub = degp - inter - corr;
                float arg = (1.0f + S1 * sub) / (1.0f + S1 * inter);
                float v = __fdividef(1.0f, 1.0f + __expf(arg));
                atomicAdd(&myT[lq], wp * eqrow[i] * (v - v0));
                atomicAdd(&myIC[lq], w);
            }
        }
        __syncthreads();
        if (tid < Cc) {
            float tT = 0.f; unsigned tIC = 0u;
#pragma unroll
            for (int w = 0; w < 4; w++) {
                tT += sTw[w * Cc + tid];
                tIC += sICw[w * Cc + tid];             // per-row Σinter < 65536
            }
            if (tid != cp) {
                int idx = cp * Cc + tid;
                if (tT != 0.f) atomicAdd(&g_T[idx], tT);
                if (tIC) {
                    atomicAdd(&g_Si[idx], (float)(tIC & 0xFFFFu));
                    atomicAdd(&g_Sc[idx], (float)(tIC >> 16));
                }
            }
            atomicAdd(&g_Qs[tid * Cc + cp], g_Eq[tid * Nn + p]);   // node as q
        }
        if (tid == 0) {
            atomicAdd(&g_Ncnt[cp], 1.f);
            atomicAdd(&g_Sdeg[cp], degp);
            atomicAdd(&g_W0[cp], wp * v0);
        }
    }

    // ===== arrival + fused final (output, then state reset for next replay) ====
    __syncthreads();
    if (tid == 0) { __threadfence(); s_last = (atomicAdd(&g_done, 1) == gridDim.x - 1); }
    __syncthreads();
    if (!s_last) return;
    __threadfence();

    float ce = 0.f;
#pragma unroll
    for (int k = 0; k < 2048 / PTPB; k++) ce += g_cepart[tid + k * PTPB];
    sred[tid] = ce;
    __syncthreads();
    for (int o = PTPB / 2; o > 0; o >>= 1) {
        if (tid < o) sred[tid] += sred[tid + o];
        __syncthreads();
    }
    float ce_tot = sred[0];
    __syncthreads();

    float contrib = 0.f;
    if (tid < Cc * Cc) {
        int i = tid / Cc, j = tid - i * Cc;
        if (i != j) {
            float Si = g_Si[tid];
            float Ssub = g_Sdeg[i] * g_Ncnt[j] - Si - g_Sc[tid];   // exact ints in f32
            if (Si > 0.f && Ssub > 0.f) {
                float T = g_T[tid] + g_W0[i] * g_Qs[tid];
                float ni = fmaxf(g_Ncnt[i], 1.f);
                float nj = fmaxf(g_Ncnt[j], 1.f);
                contrib = T / (ni * nj);
            }
        }
    }
    sred[tid] = contrib;
    __syncthreads();
    for (int o = PTPB / 2; o > 0; o >>= 1) {
        if (tid < o) sred[tid] += sred[tid + o];
        __syncthreads();
    }
    if (tid == 0) out[0] = ce_tot / (float)Nn + 0.001f * sred[0];

    // reset state for the NEXT replay (all blocks arrived; no races)
    for (int i = tid; i < Nn; i += PTPB) { g_colcnt[i] = 0; g_deg[i] = 0; g_diag[i] = 0; }
    if (tid < Cc * Cc) { g_T[tid] = 0.f; g_Si[tid] = 0.f; g_Sc[tid] = 0.f; g_Qs[tid] = 0.f; }
    if (tid < Cc) { g_Ncnt[tid] = 0.f; g_Sdeg[tid] = 0.f; g_W0[tid] = 0.f; }
    if (tid == 0) { g_done = 0; __threadfence(); }
}

// ---------------- launch -----------------------------------------------------
extern "C" void kernel_launch(void* const* d_in, const int* in_sizes, int n_in,
                              void* d_out, int out_size) {
    const float* preds  = (const float*)d_in[0];
    const int*   labels = (const int*)d_in[1];
    const unsigned int* mask = (const unsigned int*)d_in[2];
    const unsigned int* adj  = (const unsigned int*)d_in[3];

    k_build<<<2049, 256>>>(preds, labels, mask, adj);
    k_process<<<PGRID, PTPB>>>((float*)d_out);
}

// round 17
// speedup vs baseline: 1.2284x; 1.0863x over previous
#include <cuda_runtime.h>
#include <stdint.h>

#define Nn 4096
#define Cc 10
#define LMAX 128
#define S1 0.73105857863000489f      // sigmoid(1.0) in fp32
#define TCAP 768
#define PTPB 128                     // k_process threads (4 warps)
#define PGRID 2560                   // k_process grid (>= qn with wide margin)

// ---------------- scratch (static device globals; zero-initialized) ----------
// g_colcnt/g_deg/g_diag and class accumulators are zeroed by the FINAL block
// of k_process for the NEXT replay (first run uses static zero-init).
__device__ int   g_colcnt[Nn];            // masked in-neighbor count of column k
__device__ int   g_colidx[Nn * LMAX];     // masked in-neighbor NODE ids of column k
__device__ int   g_deg[Nn];               // out-degree (masked rows only)
__device__ int   g_rowidx[Nn * LMAX];     // out-neighbor node ids (masked rows)
__device__ unsigned char g_diag[Nn];      // node has self-loop
__device__ unsigned char g_slab[Nn];      // label if masked, 255 if unmasked
__device__ float g_Eq[Cc * Nn];           // exp(preds[q,i]), node-indexed
__device__ float g_Qs[Cc * Cc];
__device__ float g_T[Cc * Cc];
__device__ float g_Si[Cc * Cc];
__device__ float g_Sc[Cc * Cc];
__device__ float g_Ncnt[Cc];
__device__ float g_Sdeg[Cc];
__device__ float g_W0[Cc];
__device__ float g_cepart[2048];          // per-block CE partials (overwritten)
__device__ int   g_qn;
__device__ int   g_qlist[Nn];             // masked node ids in node order
__device__ int   g_done;                  // arrival counter (self-resetting)

// ============ Kernel 1: build + CE/Eq + rank scan (unchanged, proven) ========
__device__ __forceinline__ void decode4(uint4 x0, uint4 x1, uint4 x2, uint4 x3,
                                        int tid, int n) {
#pragma unroll
    for (int s = 0; s < 4; s++) {
        uint4 x = (s == 0) ? x0 : (s == 1) ? x1 : (s == 2) ? x2 : x3;
        if (x.x | x.y | x.z | x.w) {
            int i4 = tid + s * 256;
            unsigned parts[4] = {x.x, x.y, x.z, x.w};
#pragma unroll
            for (int u = 0; u < 4; u++) {
                if (parts[u]) {
                    int kk = i4 * 4 + u;
                    int ri = atomicAdd(&g_deg[n], 1);
                    if (ri < LMAX) g_rowidx[n * LMAX + ri] = kk;
                    int ci = atomicAdd(&g_colcnt[kk], 1);
                    if (ci < LMAX) g_colidx[kk * LMAX + ci] = n;
                    if (n == kk) g_diag[n] = 1;
                }
            }
        }
    }
}

__global__ void k_build(const float* __restrict__ preds,
                        const int* __restrict__ labels,
                        const unsigned int* __restrict__ mask,
                        const unsigned int* __restrict__ adj) {
    __shared__ float s_ce[2];
    __shared__ int s_wsum[8];
    int tid = threadIdx.x, bi = blockIdx.x;
    int lane = tid & 31, wid = tid >> 5;

    if (bi == 2048) {
        // rank scan: qlist (masked nodes in node order), qn, slab
        int base = tid * 16;
        unsigned mv = 0; int cnt = 0;
#pragma unroll
        for (int j = 0; j < 16; j++) {
            if (mask[base + j] != 0u) { mv |= 1u << j; cnt++; }
        }
        int inc = cnt;
#pragma unroll
        for (int o = 1; o < 32; o <<= 1) {
            int y = __shfl_up_sync(0xFFFFFFFFu, inc, o);
            if (lane >= o) inc += y;
        }
        if (lane == 31) s_wsum[wid] = inc;
        __syncthreads();
        int woff = 0;
#pragma unroll
        for (int k = 0; k < 8; k++) if (k < wid) woff += s_wsum[k];
        int rk = woff + inc - cnt;
#pragma unroll
        for (int j = 0; j < 16; j++) {
            int pp = base + j;
            if ((mv >> j) & 1u) {
                g_qlist[rk] = pp;
                g_slab[pp] = (unsigned char)labels[pp];
                rk++;
            } else g_slab[pp] = 255;
        }
        if (tid == 255) g_qn = rk;
        return;
    }

    int n0 = 2 * bi, n1 = 2 * bi + 1;
    bool has0 = (mask[n0] != 0u), has1 = (mask[n1] != 0u);
    const uint4* row0 = (const uint4*)(adj + (size_t)n0 * Nn);
    const uint4* row1 = (const uint4*)(adj + (size_t)n1 * Nn);
    uint4 a0, a1, a2, a3, b0, b1, b2, b3;
    if (has0) { a0 = row0[tid]; a1 = row0[tid + 256]; a2 = row0[tid + 512]; a3 = row0[tid + 768]; }
    if (has1) { b0 = row1[tid]; b1 = row1[tid + 256]; b2 = row1[tid + 512]; b3 = row1[tid + 768]; }

    // CE + Eq for this block's two nodes (warps 0/1) — hidden under adj stream
    if (wid < 2) {
        int n = 2 * bi + wid;
        float r = 0.f, e = 0.f;
        if (lane < Cc) {
            r = preds[n * Cc + lane];
            e = __expf(r);
            g_Eq[lane * Nn + n] = e;
        }
        float se = e;
#pragma unroll
        for (int o = 16; o > 0; o >>= 1) se += __shfl_down_sync(0xFFFFFFFFu, se, o);
        se = __shfl_sync(0xFFFFFFFFu, se, 0);
        int l = labels[n];
        float rl = __shfl_sync(0xFFFFFFFFu, r, l);
        if (lane == 0) s_ce[wid] = __logf(se) - rl;   // -log softmax[l]
    }
    __syncthreads();
    if (tid == 0) g_cepart[bi] = s_ce[0] + s_ce[1];

    if (has0) decode4(a0, a1, a2, a3, tid, n0);
    if (has1) decode4(b0, b1, b2, b3, tid, n1);
}

// ============ Kernel 2: one masked row per block; BYTE counters (4KB) ========
// Counter byte layout: bits 0-6 = inter count (max ~50), bit 7 = corr flag.
// Max byte value ~178 < 256 -> no cross-byte carry. First-toucher detection
// reads the pre-add byte from the atomicAdd return value.
__global__ void __launch_bounds__(PTPB, 13)
k_process(float* __restrict__ out) {
    __shared__ unsigned int scnt32[Nn / 4];   // 4KB byte counters (packed)
    __shared__ int   s_touch[TCAP];           // 3KB touched node ids
    __shared__ int   s_nbr[LMAX];             // out-neighbors of this row
    __shared__ int   s_ccnt[LMAX];            // prefetched colcnt per neighbor
    __shared__ float sTw[4 * Cc];             // per-warp T accumulators
    __shared__ unsigned int sICw[4 * Cc];     // per-warp packed (corr<<16|inter)
    __shared__ float sred[PTPB];
    __shared__ int   s_last, s_ntouch, s_ovf;

    const int tid = threadIdx.x, bi = blockIdx.x;
    const int lane = tid & 31, wid = tid >> 5;
    const int qn = g_qn;

    if (bi < qn) {
        const int p = g_qlist[bi];
        if (tid == 0) { s_ntouch = 0; s_ovf = 0; }
        if (tid < 4 * Cc) { sTw[tid] = 0.f; sICw[tid] = 0u; }
        {   // zero byte counters (4KB)
            uint4* s4 = (uint4*)scnt32;
            for (int i = tid; i < Nn / 16; i += PTPB) s4[i] = make_uint4(0, 0, 0, 0);
        }
        int dgi = g_deg[p];
        int dp = min(dgi, LMAX);
        int my_nbr = -1;
        if (tid < dp) {
            my_nbr = g_rowidx[p * LMAX + tid];
            s_nbr[tid] = my_nbr;
            s_ccnt[tid] = g_colcnt[my_nbr];    // prefetched in parallel
        }
        __syncthreads();
        int cp = (int)g_slab[p];

        // expansion: 4 warps over out-neighbors; warp-aggregated appends
        for (int i = wid; i < dp; i += 4) {
            int k = s_nbr[i];
            int c = min(s_ccnt[i], LMAX);
            const int* cl = g_colidx + k * LMAX;
            for (int jj = 0; jj < c; jj += 32) {
                int j = jj + lane;
                int nd = 0; bool first = false;
                if (j < c) {
                    nd = cl[j];
                    int sh = (nd & 3) * 8;
                    unsigned old = atomicAdd(&scnt32[nd >> 2], 1u << sh);
                    first = (((old >> sh) & 0xFFu) == 0u);
                }
                unsigned ball = __ballot_sync(0xFFFFFFFFu, first);
                if (ball) {
                    int leader = __ffs(ball) - 1;
                    int base = 0;
                    if (lane == leader) base = atomicAdd(&s_ntouch, __popc(ball));
                    base = __shfl_sync(0xFFFFFFFFu, base, leader);
                    if (first) {
                        int off = __popc(ball & ((1u << lane) - 1u));
                        if (base + off < TCAP) s_touch[base + off] = nd; else s_ovf = 1;
                    }
                }
            }
        }
        // corr flags: masked out-neighbors lacking a self-loop (dp <= PTPB)
        {
            int q = my_nbr; bool first = false;
            if (q >= 0 && g_slab[q] != 255 && !g_diag[q]) {
                int sh = (q & 3) * 8;
                unsigned old = atomicAdd(&scnt32[q >> 2], 128u << sh);
                first = (((old >> sh) & 0xFFu) == 0u);
            }
            unsigned ball = __ballot_sync(0xFFFFFFFFu, first);
            if (ball) {
                int leader = __ffs(ball) - 1;
                int base = 0;
                if (lane == leader) base = atomicAdd(&s_ntouch, __popc(ball));
                base = __shfl_sync(0xFFFFFFFFu, base, leader);
                if (first) {
                    int off = __popc(ball & ((1u << lane) - 1u));
                    if (base + off < TCAP) s_touch[base + off] = my_nbr; else s_ovf = 1;
                }
            }
        }
        __syncthreads();

        float degp = (float)dgi;
        float wp = __fdividef(1.f, g_Eq[cp * Nn + p]);          // exp(-pos)
        float v0 = __fdividef(1.f, 1.f + __expf(1.f + S1 * degp));
        const float* eqrow = g_Eq + cp * Nn;
        float* myT = sTw + wid * Cc;
        unsigned int* myIC = sICw + wid * Cc;

        if (!s_ovf) {
            int nt = s_ntouch;
            for (int j = tid; j < nt; j += PTPB) {
                int i = s_touch[j];
                unsigned b = (scnt32[i >> 2] >> ((i & 3) * 8)) & 0xFFu;
                int lq = (int)g_slab[i];
                if (lq == cp) continue;                // same class never used
                float inter = (float)(b & 0x7Fu);
                float corr  = (float)(b >> 7);
                float sub = degp - inter - corr;
                float arg = (1.0f + S1 * sub) / (1.0f + S1 * inter);
                float v = __fdividef(1.0f, 1.0f + __expf(arg));
                atomicAdd(&myT[lq], wp * eqrow[i] * (v - v0));
                atomicAdd(&myIC[lq], (b >> 7 << 16) | (b & 0x7Fu));
            }
        } else {                                       // fallback: dense scan
            for (int i = tid; i < Nn; i += PTPB) {
                unsigned b = (scnt32[i >> 2] >> ((i & 3) * 8)) & 0xFFu;
                if (!b) continue;
                int lq = (int)g_slab[i];
                if (lq == 255 || lq == cp) continue;
                float inter = (float)(b & 0x7Fu);
                float corr  = (float)(b >> 7);
                float sub = degp - inter - corr;
                float arg = (1.0f + S1 * sub) / (1.0f + S1 * inter);
                float v = __fdividef(1.0f, 1.0f + __expf(arg));
                atomicAdd(&myT[lq], wp * eqrow[i] * (v - v0));
                atomicAdd(&myIC[lq], (b >> 7 << 16) | (b & 0x7Fu));
            }
        }
        __syncthreads();
        if (tid < Cc) {
            float tT = 0.f; unsigned tIC = 0u;
#pragma unroll
            for (int w = 0; w < 4; w++) {
                tT += sTw[w * Cc + tid];
                tIC += sICw[w * Cc + tid];             // per-row Σinter < 65536
            }
            if (tid != cp) {
                int idx = cp * Cc + tid;
                if (tT != 0.f) atomicAdd(&g_T[idx], tT);
                if (tIC) {
                    atomicAdd(&g_Si[idx], (float)(tIC & 0xFFFFu));
                    atomicAdd(&g_Sc[idx], (float)(tIC >> 16));
                }
            }
            atomicAdd(&g_Qs[tid * Cc + cp], g_Eq[tid * Nn + p]);   // node as q
        }
        if (tid == 0) {
            atomicAdd(&g_Ncnt[cp], 1.f);
            atomicAdd(&g_Sdeg[cp], degp);
            atomicAdd(&g_W0[cp], wp * v0);
        }
    }

    // ===== arrival + fused final (output, then state reset for next replay) ====
    __syncthreads();
    if (tid == 0) { __threadfence(); s_last = (atomicAdd(&g_done, 1) == gridDim.x - 1); }
    __syncthreads();
    if (!s_last) return;
    __threadfence();

    float ce = 0.f;
#pragma unroll
    for (int k = 0; k < 2048 / PTPB; k++) ce += g_cepart[tid + k * PTPB];
    sred[tid] = ce;
    __syncthreads();
    for (int o = PTPB / 2; o > 0; o >>= 1) {
        if (tid < o) sred[tid] += sred[tid + o];
        __syncthreads();
    }
    float ce_tot = sred[0];
    __syncthreads();

    float contrib = 0.f;
    if (tid < Cc * Cc) {
        int i = tid / Cc, j = tid - i * Cc;
        if (i != j) {
            float Si = g_Si[tid];
            float Ssub = g_Sdeg[i] * g_Ncnt[j] - Si - g_Sc[tid];   // exact ints in f32
            if (Si > 0.f && Ssub > 0.f) {
                float T = g_T[tid] + g_W0[i] * g_Qs[tid];
                float ni = fmaxf(g_Ncnt[i], 1.f);
                float nj = fmaxf(g_Ncnt[j], 1.f);
                contrib = T / (ni * nj);
            }
        }
    }
    sred[tid] = contrib;
    __syncthreads();
    for (int o = PTPB / 2; o > 0; o >>= 1) {
        if (tid < o) sred[tid] += sred[tid + o];
        __syncthreads();
    }
    if (tid == 0) out[0] = ce_tot / (float)Nn + 0.001f * sred[0];

    // reset state for the NEXT replay (all blocks arrived; no races)
    for (int i = tid; i < Nn; i += PTPB) { g_colcnt[i] = 0; g_deg[i] = 0; g_diag[i] = 0; }
    if (tid < Cc * Cc) { g_T[tid] = 0.f; g_Si[tid] = 0.f; g_Sc[tid] = 0.f; g_Qs[tid] = 0.f; }
    if (tid < Cc) { g_Ncnt[tid] = 0.f; g_Sdeg[tid] = 0.f; g_W0[tid] = 0.f; }
    if (tid == 0) { g_done = 0; __threadfence(); }
}

// ---------------- launch -----------------------------------------------------
extern "C" void kernel_launch(void* const* d_in, const int* in_sizes, int n_in,
                              void* d_out, int out_size) {
    const float* preds  = (const float*)d_in[0];
    const int*   labels = (const int*)d_in[1];
    const unsigned int* mask = (const unsigned int*)d_in[2];
    const unsigned int* adj  = (const unsigned int*)d_in[3];

    k_build<<<2049, 256>>>(preds, labels, mask, adj);
    k_process<<<PGRID, PTPB>>>((float*)d_out);
}